// round 10
// baseline (speedup 1.0000x reference)
#include <cuda_runtime.h>
#include <cuda_bf16.h>
#include <cstdint>

// Problem constants
#define NPTS   1048576
#define CIN    64
#define COUT   96
#define NB     4
#define NSEG2  1048576   // 4 * 64^3
#define NSEG4  131072    // 4 * 32^3
#define NSEG8  16384     // 4 * 16^3

// ---------------- static device scratch ----------------
__device__ float g_sums2[(long)NSEG2 * 64];   // 268 MB
__device__ float g_cnt2[NSEG2];
__device__ float g_sums4[(long)NSEG4 * 64];   // 33.5 MB
__device__ float g_cnt4[NSEG4];
__device__ float g_sums8[(long)NSEG8 * 64];   // 4 MB
__device__ float g_cnt8[NSEG8];
__device__ float g_base0[NB * COUT];
__device__ float g_Z8[(long)NSEG8 * COUT];    // 6.3 MB
__device__ float g_Z4[(long)NSEG4 * COUT];    // 50 MB
__device__ int   g_seg2[NPTS];
// pre-split W blocks (levels 2,4,8), packed bf16x2: [L][o][j], j = k/2
__device__ uint32_t g_Wh32[3 * 96 * 32];
__device__ uint32_t g_Wl32[3 * 96 * 32];

// ---------------- PTX helpers ----------------
__device__ __forceinline__ void red_add_v4(float* addr, float4 v) {
    asm volatile("red.global.add.v4.f32 [%0], {%1, %2, %3, %4};"
                 :: "l"(addr), "f"(v.x), "f"(v.y), "f"(v.z), "f"(v.w)
                 : "memory");
}

__device__ __forceinline__ void hmma16816(
    float& c0, float& c1, float& c2, float& c3,
    uint32_t a0, uint32_t a1, uint32_t a2, uint32_t a3,
    uint32_t b0, uint32_t b1)
{
    asm volatile(
        "mma.sync.aligned.m16n8k16.row.col.f32.bf16.bf16.f32 "
        "{%0,%1,%2,%3}, {%4,%5,%6,%7}, {%8,%9}, {%0,%1,%2,%3};"
        : "+f"(c0), "+f"(c1), "+f"(c2), "+f"(c3)
        : "r"(a0), "r"(a1), "r"(a2), "r"(a3), "r"(b0), "r"(b1));
}

// split float pair into (hi bf16x2, lo bf16x2)
__device__ __forceinline__ void split2(float x, float y, uint32_t& hi, uint32_t& lo) {
    __nv_bfloat16 hx = __float2bfloat16_rn(x);
    __nv_bfloat16 hy = __float2bfloat16_rn(y);
    __nv_bfloat16 lx = __float2bfloat16_rn(x - __bfloat162float(hx));
    __nv_bfloat16 ly = __float2bfloat16_rn(y - __bfloat162float(hy));
    __nv_bfloat162 h = {hx, hy};
    __nv_bfloat162 l = {lx, ly};
    hi = *(uint32_t*)&h;
    lo = *(uint32_t*)&l;
}

// ---------------- kernel 0: pre-split W into bf16 hi/lo tables ----------------
__global__ __launch_bounds__(256) void split_w_kernel(const float* __restrict__ W) {
    int idx = blockIdx.x * 256 + threadIdx.x;   // 3*96*32 = 9216
    if (idx >= 9216) return;
    int L = idx / 3072;
    int r = idx - L * 3072;
    int o = r >> 5, j = r & 31;
    const float* src = W + o * 256 + 64 + L * 64 + 2 * j;
    uint32_t h, l;
    split2(src[0], src[1], h, l);
    g_Wh32[idx] = h;
    g_Wl32[idx] = l;
}

// ---------------- kernel 1: zero level-2 scratch only ----------------
__global__ void zero_kernel() {
    long tid = (long)blockIdx.x * blockDim.x + threadIdx.x;
    long stride = (long)gridDim.x * blockDim.x;
    float4 z = make_float4(0.f, 0.f, 0.f, 0.f);
    float4* s2 = (float4*)g_sums2;
    for (long i = tid; i < (long)NSEG2 * 16; i += stride) s2[i] = z;
    float4* c2 = (float4*)g_cnt2;
    for (long i = tid; i < NSEG2 / 4; i += stride) c2[i] = z;
}

// ---------------- kernel 2: scatter into level-2 ONLY ----------------
__global__ __launch_bounds__(256) void scatter_kernel(
    const float4* __restrict__ feats4,
    const int* __restrict__ coords,
    const int* __restrict__ batch)
{
    int p = blockIdx.x * 256 + threadIdx.x;
    if (p >= NPTS) return;
    int x = coords[3 * p + 0];
    int y = coords[3 * p + 1];
    int z = coords[3 * p + 2];
    int b = batch[p];

    int s2 = (b << 18) | ((x >> 1) << 12) | ((y >> 1) << 6) | (z >> 1);
    g_seg2[p] = s2;
    atomicAdd(&g_cnt2[s2], 1.0f);

    float* p2 = &g_sums2[(long)s2 * 64];
    const float4* f = feats4 + (long)p * 16;
#pragma unroll
    for (int i = 0; i < 16; i++) {
        red_add_v4(p2 + 4 * i, f[i]);
    }
}

// ---------------- kernel 2b: hierarchical reductions ----------------
__global__ __launch_bounds__(256) void reduce4_kernel() {
    int t = blockIdx.x * 256 + threadIdx.x;   // NSEG4 * 16 tasks
    int kc = t & 15;
    int s4 = t >> 4;
    int b = s4 >> 15, x = (s4 >> 10) & 31, y = (s4 >> 5) & 31, z = s4 & 31;
    int base = (b << 18) | ((x << 1) << 12) | ((y << 1) << 6) | (z << 1);
    float4 acc = make_float4(0.f, 0.f, 0.f, 0.f);
#pragma unroll
    for (int d = 0; d < 8; d++) {
        int s2 = base + (((d >> 2) & 1) << 12) + (((d >> 1) & 1) << 6) + (d & 1);
        float4 v = *(const float4*)&g_sums2[(long)s2 * 64 + kc * 4];
        acc.x += v.x; acc.y += v.y; acc.z += v.z; acc.w += v.w;
    }
    *(float4*)&g_sums4[(long)s4 * 64 + kc * 4] = acc;
    if (kc == 0) {
        float c = 0.f;
#pragma unroll
        for (int d = 0; d < 8; d++)
            c += g_cnt2[base + (((d >> 2) & 1) << 12) + (((d >> 1) & 1) << 6) + (d & 1)];
        g_cnt4[s4] = c;
    }
}

__global__ __launch_bounds__(256) void reduce8_kernel() {
    int t = blockIdx.x * 256 + threadIdx.x;   // NSEG8 * 16 tasks
    int kc = t & 15;
    int s8 = t >> 4;
    int b = s8 >> 12, x = (s8 >> 8) & 15, y = (s8 >> 4) & 15, z = s8 & 15;
    int base = (b << 15) | ((x << 1) << 10) | ((y << 1) << 5) | (z << 1);
    float4 acc = make_float4(0.f, 0.f, 0.f, 0.f);
#pragma unroll
    for (int d = 0; d < 8; d++) {
        int s4 = base + (((d >> 2) & 1) << 10) + (((d >> 1) & 1) << 5) + (d & 1);
        float4 v = *(const float4*)&g_sums4[(long)s4 * 64 + kc * 4];
        acc.x += v.x; acc.y += v.y; acc.z += v.z; acc.w += v.w;
    }
    *(float4*)&g_sums8[(long)s8 * 64 + kc * 4] = acc;
    if (kc == 0) {
        float c = 0.f;
#pragma unroll
        for (int d = 0; d < 8; d++)
            c += g_cnt4[base + (((d >> 2) & 1) << 10) + (((d >> 1) & 1) << 5) + (d & 1)];
        g_cnt8[s8] = c;
    }
}

// ---------------- kernel 3: level-0 reduce + base projection ----------------
__global__ __launch_bounds__(256) void l0_kernel(
    const float* __restrict__ W, const float* __restrict__ bias)
{
    int b = blockIdx.x;
    int tid = threadIdx.x;
    __shared__ float sm[4][64];
    __shared__ float smean[64];
    __shared__ float scnt[256];

    int c = tid & 63, g = tid >> 6;
    const float* base = g_sums8 + (long)b * 4096 * 64;
    float acc = 0.f;
    for (int s = g; s < 4096; s += 4) acc += base[s * 64 + c];
    sm[g][c] = acc;

    float ca = 0.f;
    for (int s = tid; s < 4096; s += 256) ca += g_cnt8[b * 4096 + s];
    scnt[tid] = ca;
    __syncthreads();

    for (int off = 128; off > 0; off >>= 1) {
        if (tid < off) scnt[tid] += scnt[tid + off];
        __syncthreads();
    }
    if (tid < 64) {
        smean[tid] = (sm[0][tid] + sm[1][tid] + sm[2][tid] + sm[3][tid])
                   / fmaxf(scnt[0], 1.0f);
    }
    __syncthreads();
    if (tid < 96) {
        float a = bias[tid];
        const float* wr = W + tid * 256;  // global block = cols [0,64)
#pragma unroll 8
        for (int k = 0; k < 64; k++) a += wr[k] * smean[k];
        g_base0[b * COUT + tid] = a;
    }
}

// ---------------- shared HMMA tile machinery ----------------
#define A_STRIDE 72   // halves per A row, padded
#define B_U32    36   // uint32 per B row (padded)
#define TILE_PTS 128  // points/segments per block
#define TTHREADS 256  // threads per block (8 warps)

// dynamic smem layout (bytes):
//   [0)                         Ah: TILE_PTS*A_STRIDE bf16 = 18432
//   [18432)                     Al: 18432
//   [36864)                     Bh: 96*B_U32 u32 = 13824
//   [50688)                     Bl: 13824
//   total 64512
#define SMEM_AH_OFF 0
#define SMEM_AL_OFF (TILE_PTS * A_STRIDE * 2)
#define SMEM_BH_OFF (2 * TILE_PTS * A_STRIDE * 2)
#define SMEM_BL_OFF (SMEM_BH_OFF + 96 * B_U32 * 4)
#define SMEM_DYN    (SMEM_BL_OFF + 96 * B_U32 * 4)

// stage pre-split W level block into smem (conflict-free layout)
__device__ __forceinline__ void stage_W(uint32_t* shBh, uint32_t* shBl,
                                        const uint32_t* __restrict__ Wh,
                                        const uint32_t* __restrict__ Wl,
                                        int tid)
{
    for (int idx = tid; idx < 3072; idx += TTHREADS) {
        int o = idx >> 5, j = idx & 31;
        shBh[o * B_U32 + j] = Wh[idx];
        shBl[o * B_U32 + j] = Wl[idx];
    }
}

// core bf16x3 MMA over staged A (TILE_PTS rows) and W (96 rows), per-warp m16 x n96
__device__ __forceinline__ void mma_tile(
    const __nv_bfloat16* shAh, const __nv_bfloat16* shAl,
    const uint32_t* shBh, const uint32_t* shBl,
    int warp_m, int grp, int qid, float acc[12][4])
{
#pragma unroll
    for (int ks = 0; ks < 4; ks++) {
        int k0 = ks * 16 + qid * 2;
        int ra = (warp_m + grp) * A_STRIDE;
        int rb = (warp_m + grp + 8) * A_STRIDE;
        uint32_t ah0 = *(const uint32_t*)&shAh[ra + k0];
        uint32_t ah1 = *(const uint32_t*)&shAh[rb + k0];
        uint32_t ah2 = *(const uint32_t*)&shAh[ra + k0 + 8];
        uint32_t ah3 = *(const uint32_t*)&shAh[rb + k0 + 8];
        uint32_t al0 = *(const uint32_t*)&shAl[ra + k0];
        uint32_t al1 = *(const uint32_t*)&shAl[rb + k0];
        uint32_t al2 = *(const uint32_t*)&shAl[ra + k0 + 8];
        uint32_t al3 = *(const uint32_t*)&shAl[rb + k0 + 8];
        int wb = ks * 8 + qid;
#pragma unroll
        for (int t = 0; t < 12; t++) {
            int n = t * 8 + grp;
            uint32_t bh0 = shBh[n * B_U32 + wb];
            uint32_t bh1 = shBh[n * B_U32 + wb + 4];
            uint32_t bl0 = shBl[n * B_U32 + wb];
            uint32_t bl1 = shBl[n * B_U32 + wb + 4];
            hmma16816(acc[t][0], acc[t][1], acc[t][2], acc[t][3],
                      ah0, ah1, ah2, ah3, bh0, bh1);
            hmma16816(acc[t][0], acc[t][1], acc[t][2], acc[t][3],
                      ah0, ah1, ah2, ah3, bl0, bl1);
            hmma16816(acc[t][0], acc[t][1], acc[t][2], acc[t][3],
                      al0, al1, al2, al3, bh0, bh1);
        }
    }
}

// ---------------- HMMA transform for levels 8 and 4 (bf16x3) ----------------
template <int LEVEL>
__global__ __launch_bounds__(TTHREADS) void transform_hmma_kernel()
{
    extern __shared__ __align__(16) char dynsmem[];
    __nv_bfloat16* sh_Ah = (__nv_bfloat16*)(dynsmem + SMEM_AH_OFF);
    __nv_bfloat16* sh_Al = (__nv_bfloat16*)(dynsmem + SMEM_AL_OFF);
    uint32_t* sh_Bh = (uint32_t*)(dynsmem + SMEM_BH_OFF);
    uint32_t* sh_Bl = (uint32_t*)(dynsmem + SMEM_BL_OFF);

    int tid  = threadIdx.x;
    int wid  = tid >> 5;
    int lane = tid & 31;
    int base = blockIdx.x * TILE_PTS;

    const float* SUMS = (LEVEL == 4) ? g_sums4 : g_sums8;
    const float* CNT  = (LEVEL == 4) ? g_cnt4  : g_cnt8;
    const int LIDX = (LEVEL == 4) ? 1 : 2;

    stage_W(sh_Bh, sh_Bl, g_Wh32 + LIDX * 3072, g_Wl32 + LIDX * 3072, tid);

    for (int it = tid; it < TILE_PTS * 16; it += TTHREADS) {
        int slot = it >> 4, kc = it & 15;
        int s = base + slot;
        float inv = 1.0f / fmaxf(CNT[s], 1.0f);
        float4 v = *(const float4*)&SUMS[(long)s * 64 + kc * 4];
        uint32_t h0, l0, h1, l1;
        split2(v.x * inv, v.y * inv, h0, l0);
        split2(v.z * inv, v.w * inv, h1, l1);
        uint32_t* dh = (uint32_t*)&sh_Ah[slot * A_STRIDE + kc * 4];
        uint32_t* dl = (uint32_t*)&sh_Al[slot * A_STRIDE + kc * 4];
        dh[0] = h0; dh[1] = h1;
        dl[0] = l0; dl[1] = l1;
    }
    __syncthreads();

    int warp_m = wid * 16;
    int grp = lane >> 2;
    int qid = lane & 3;

    float acc[12][4];
#pragma unroll
    for (int t = 0; t < 12; t++)
#pragma unroll
        for (int j = 0; j < 4; j++) acc[t][j] = 0.f;

    mma_tile(sh_Ah, sh_Al, sh_Bh, sh_Bl, warp_m, grp, qid, acc);

    // epilogue
    int slot0 = warp_m + grp;
    int slot1 = slot0 + 8;
    int s0 = base + slot0;
    int s1 = base + slot1;

    const float* p0;
    const float* p1;
    float* zout;
    if (LEVEL == 8) {
        p0 = &g_base0[(s0 >> 12) * COUT];
        p1 = &g_base0[(s1 >> 12) * COUT];
        zout = g_Z8;
    } else {
        int bb0 = s0 >> 15, xx0 = (s0 >> 10) & 31, yy0 = (s0 >> 5) & 31, zz0 = s0 & 31;
        int bb1 = s1 >> 15, xx1 = (s1 >> 10) & 31, yy1 = (s1 >> 5) & 31, zz1 = s1 & 31;
        p0 = &g_Z8[(long)((bb0 << 12) | ((xx0 >> 1) << 8) | ((yy0 >> 1) << 4) | (zz0 >> 1)) * COUT];
        p1 = &g_Z8[(long)((bb1 << 12) | ((xx1 >> 1) << 8) | ((yy1 >> 1) << 4) | (zz1 >> 1)) * COUT];
        zout = g_Z4;
    }
    float* d0 = zout + (long)s0 * COUT;
    float* d1 = zout + (long)s1 * COUT;

#pragma unroll
    for (int t = 0; t < 12; t++) {
        int c = t * 8 + qid * 2;
        float2 za = *(const float2*)&p0[c];
        float2 zb = *(const float2*)&p1[c];
        *(float2*)&d0[c] = make_float2(acc[t][0] + za.x, acc[t][1] + za.y);
        *(float2*)&d1[c] = make_float2(acc[t][2] + zb.x, acc[t][3] + zb.y);
    }
}

// ---------------- fused level-2 transform + output (bf16x3 HMMA) ----------------
__global__ __launch_bounds__(TTHREADS) void fused_mma_kernel(float* __restrict__ out)
{
    extern __shared__ __align__(16) char dynsmem[];
    __nv_bfloat16* sh_Ah = (__nv_bfloat16*)(dynsmem + SMEM_AH_OFF);
    __nv_bfloat16* sh_Al = (__nv_bfloat16*)(dynsmem + SMEM_AL_OFF);
    uint32_t* sh_Bh = (uint32_t*)(dynsmem + SMEM_BH_OFF);
    uint32_t* sh_Bl = (uint32_t*)(dynsmem + SMEM_BL_OFF);

    __shared__ int   s_s4[TILE_PTS];
    __shared__ int   s_sid[TILE_PTS];
    __shared__ float s_inv[TILE_PTS];

    int tid  = threadIdx.x;
    int wid  = tid >> 5;
    int lane = tid & 31;
    int pbase = blockIdx.x * TILE_PTS;

    if (tid < TILE_PTS) {
        int s2 = g_seg2[pbase + tid];
        s_sid[tid] = s2;
        int bb = s2 >> 18, xx = (s2 >> 12) & 63, yy = (s2 >> 6) & 63, zz = s2 & 63;
        s_s4[tid] = (bb << 15) | ((xx >> 1) << 10) | ((yy >> 1) << 5) | (zz >> 1);
        s_inv[tid] = 1.0f / fmaxf(g_cnt2[s2], 1.0f);
    }

    stage_W(sh_Bh, sh_Bl, g_Wh32, g_Wl32, tid);   // level-2 block (LIDX 0)
    __syncthreads();

    // stage A: TILE_PTS mean rows -> bf16 hi/lo
    for (int it = tid; it < TILE_PTS * 16; it += TTHREADS) {
        int slot = it >> 4, kc = it & 15;
        int s = s_sid[slot];
        float inv = s_inv[slot];
        float4 v = *(const float4*)&g_sums2[(long)s * 64 + kc * 4];
        uint32_t h0, l0, h1, l1;
        split2(v.x * inv, v.y * inv, h0, l0);
        split2(v.z * inv, v.w * inv, h1, l1);
        uint32_t* dh = (uint32_t*)&sh_Ah[slot * A_STRIDE + kc * 4];
        uint32_t* dl = (uint32_t*)&sh_Al[slot * A_STRIDE + kc * 4];
        dh[0] = h0; dh[1] = h1;
        dl[0] = l0; dl[1] = l1;
    }
    __syncthreads();

    int warp_m = wid * 16;
    int grp = lane >> 2;
    int qid = lane & 3;

    float acc[12][4];
#pragma unroll
    for (int t = 0; t < 12; t++)
#pragma unroll
        for (int j = 0; j < 4; j++) acc[t][j] = 0.f;

    mma_tile(sh_Ah, sh_Al, sh_Bh, sh_Bl, warp_m, grp, qid, acc);

    // epilogue: out[p] = Z4[s4(p)] + D[p]
    int slot0 = warp_m + grp;
    int slot1 = slot0 + 8;
    const float* z0 = &g_Z4[(long)s_s4[slot0] * COUT];
    const float* z1 = &g_Z4[(long)s_s4[slot1] * COUT];
    float* d0 = out + (long)(pbase + slot0) * COUT;
    float* d1 = out + (long)(pbase + slot1) * COUT;

#pragma unroll
    for (int t = 0; t < 12; t++) {
        int c = t * 8 + qid * 2;
        float2 za = *(const float2*)&z0[c];
        float2 zb = *(const float2*)&z1[c];
        *(float2*)&d0[c] = make_float2(acc[t][0] + za.x, acc[t][1] + za.y);
        *(float2*)&d1[c] = make_float2(acc[t][2] + zb.x, acc[t][3] + zb.y);
    }
}

// ---------------- launcher ----------------
extern "C" void kernel_launch(void* const* d_in, const int* in_sizes, int n_in,
                              void* d_out, int out_size)
{
    const float* feats  = (const float*)d_in[0];
    const int*   coords = (const int*)d_in[1];
    const int*   batch  = (const int*)d_in[2];
    const float* W      = (const float*)d_in[3];
    const float* bias   = (const float*)d_in[4];

    // opt into >48KB dynamic smem (attribute set, not an allocation; idempotent)
    static bool attr_done = false;
    if (!attr_done) {
        cudaFuncSetAttribute(fused_mma_kernel,
                             cudaFuncAttributeMaxDynamicSharedMemorySize, SMEM_DYN);
        cudaFuncSetAttribute(transform_hmma_kernel<4>,
                             cudaFuncAttributeMaxDynamicSharedMemorySize, SMEM_DYN);
        cudaFuncSetAttribute(transform_hmma_kernel<8>,
                             cudaFuncAttributeMaxDynamicSharedMemorySize, SMEM_DYN);
        attr_done = true;
    }

    zero_kernel<<<2048, 256>>>();
    split_w_kernel<<<36, 256>>>(W);
    scatter_kernel<<<NPTS / 256, 256>>>((const float4*)feats, coords, batch);
    reduce4_kernel<<<(NSEG4 * 16) / 256, 256>>>();
    reduce8_kernel<<<(NSEG8 * 16) / 256, 256>>>();
    l0_kernel<<<NB, 256>>>(W, bias);
    transform_hmma_kernel<8><<<NSEG8 / TILE_PTS, TTHREADS, SMEM_DYN>>>();
    transform_hmma_kernel<4><<<NSEG4 / TILE_PTS, TTHREADS, SMEM_DYN>>>();
    fused_mma_kernel<<<NPTS / TILE_PTS, TTHREADS, SMEM_DYN>>>((float*)d_out);
}

// round 11
// speedup vs baseline: 1.1566x; 1.1566x over previous
#include <cuda_runtime.h>
#include <cuda_bf16.h>
#include <cstdint>

// Problem constants
#define NPTS   1048576
#define CIN    64
#define COUT   96
#define NB     4
#define NSEG2  1048576   // 4 * 64^3
#define NSEG4  131072    // 4 * 32^3
#define NSEG8  16384     // 4 * 16^3

// ---------------- static device scratch ----------------
__device__ float g_sums2[(long)NSEG2 * 64];   // 268 MB
__device__ float g_cnt2[NSEG2];
__device__ float g_sums4[(long)NSEG4 * 64];   // 33.5 MB
__device__ float g_cnt4[NSEG4];
__device__ float g_sums8[(long)NSEG8 * 64];   // 4 MB
__device__ float g_cnt8[NSEG8];
__device__ float g_base0[NB * COUT];
__device__ float g_Z8[(long)NSEG8 * COUT];    // 6.3 MB
__device__ float g_Z4[(long)NSEG4 * COUT];    // 50 MB
__device__ int   g_seg2[NPTS];
// pre-split W blocks (levels 2,4,8), packed bf16x2: [L][o][j], j = k/2
__device__ uint32_t g_Wh32[3 * 96 * 32];
__device__ uint32_t g_Wl32[3 * 96 * 32];

// ---------------- PTX helpers ----------------
__device__ __forceinline__ void red_add_v4(float* addr, float4 v) {
    asm volatile("red.global.add.v4.f32 [%0], {%1, %2, %3, %4};"
                 :: "l"(addr), "f"(v.x), "f"(v.y), "f"(v.z), "f"(v.w)
                 : "memory");
}

__device__ __forceinline__ void hmma16816(
    float& c0, float& c1, float& c2, float& c3,
    uint32_t a0, uint32_t a1, uint32_t a2, uint32_t a3,
    uint32_t b0, uint32_t b1)
{
    asm volatile(
        "mma.sync.aligned.m16n8k16.row.col.f32.bf16.bf16.f32 "
        "{%0,%1,%2,%3}, {%4,%5,%6,%7}, {%8,%9}, {%0,%1,%2,%3};"
        : "+f"(c0), "+f"(c1), "+f"(c2), "+f"(c3)
        : "r"(a0), "r"(a1), "r"(a2), "r"(a3), "r"(b0), "r"(b1));
}

// split float pair into (hi bf16x2, lo bf16x2)
__device__ __forceinline__ void split2(float x, float y, uint32_t& hi, uint32_t& lo) {
    __nv_bfloat16 hx = __float2bfloat16_rn(x);
    __nv_bfloat16 hy = __float2bfloat16_rn(y);
    __nv_bfloat16 lx = __float2bfloat16_rn(x - __bfloat162float(hx));
    __nv_bfloat16 ly = __float2bfloat16_rn(y - __bfloat162float(hy));
    __nv_bfloat162 h = {hx, hy};
    __nv_bfloat162 l = {lx, ly};
    hi = *(uint32_t*)&h;
    lo = *(uint32_t*)&l;
}

// ---------------- kernel 1a: zero sums2 ----------------
__global__ void zero_sums_kernel() {
    long tid = (long)blockIdx.x * blockDim.x + threadIdx.x;
    long stride = (long)gridDim.x * blockDim.x;
    float4 z = make_float4(0.f, 0.f, 0.f, 0.f);
    float4* s2 = (float4*)g_sums2;
    for (long i = tid; i < (long)NSEG2 * 16; i += stride) s2[i] = z;
}

// ---------------- kernel 1b: zero cnt2 ----------------
__global__ void zero_cnt_kernel() {
    long tid = (long)blockIdx.x * blockDim.x + threadIdx.x;
    long stride = (long)gridDim.x * blockDim.x;
    float4 z = make_float4(0.f, 0.f, 0.f, 0.f);
    float4* c2 = (float4*)g_cnt2;
    for (long i = tid; i < NSEG2 / 4; i += stride) c2[i] = z;
}

// ---------------- kernel 0: pre-split W into bf16 hi/lo tables ----------------
__global__ __launch_bounds__(256) void split_w_kernel(const float* __restrict__ W) {
    int idx = blockIdx.x * 256 + threadIdx.x;   // 3*96*32 = 9216
    if (idx >= 9216) return;
    int L = idx / 3072;
    int r = idx - L * 3072;
    int o = r >> 5, j = r & 31;
    const float* src = W + o * 256 + 64 + L * 64 + 2 * j;
    uint32_t h, l;
    split2(src[0], src[1], h, l);
    g_Wh32[idx] = h;
    g_Wl32[idx] = l;
}

// ---------------- kernel 2: chunk-parallel scatter into level-2 ----------------
// 16 threads per point; each thread handles one float4 chunk.
// Coalesced feats loads (4 lines/warp-instr) and coalesced red.v4 (4 lines/warp-instr).
__global__ __launch_bounds__(256) void scatter_kernel(
    const float4* __restrict__ feats4,
    const int* __restrict__ coords,
    const int* __restrict__ batch)
{
    const long TOTAL = (long)NPTS * 16;
    long stride = (long)gridDim.x * blockDim.x;
    for (long idx = (long)blockIdx.x * blockDim.x + threadIdx.x; idx < TOTAL; idx += stride) {
        int p  = (int)(idx >> 4);
        int kc = (int)(idx & 15);
        int x = coords[3 * p + 0];
        int y = coords[3 * p + 1];
        int z = coords[3 * p + 2];
        int b = batch[p];
        int s2 = (b << 18) | ((x >> 1) << 12) | ((y >> 1) << 6) | (z >> 1);
        if (kc == 0) {
            g_seg2[p] = s2;
            atomicAdd(&g_cnt2[s2], 1.0f);
        }
        float4 v = feats4[(long)p * 16 + kc];
        red_add_v4(&g_sums2[(long)s2 * 64 + kc * 4], v);
    }
}

// ---------------- kernel 2b: hierarchical reductions ----------------
__global__ __launch_bounds__(256) void reduce4_kernel() {
    int t = blockIdx.x * 256 + threadIdx.x;   // NSEG4 * 16 tasks
    int kc = t & 15;
    int s4 = t >> 4;
    int b = s4 >> 15, x = (s4 >> 10) & 31, y = (s4 >> 5) & 31, z = s4 & 31;
    int base = (b << 18) | ((x << 1) << 12) | ((y << 1) << 6) | (z << 1);
    float4 acc = make_float4(0.f, 0.f, 0.f, 0.f);
#pragma unroll
    for (int d = 0; d < 8; d++) {
        int s2 = base + (((d >> 2) & 1) << 12) + (((d >> 1) & 1) << 6) + (d & 1);
        float4 v = *(const float4*)&g_sums2[(long)s2 * 64 + kc * 4];
        acc.x += v.x; acc.y += v.y; acc.z += v.z; acc.w += v.w;
    }
    *(float4*)&g_sums4[(long)s4 * 64 + kc * 4] = acc;
    if (kc == 0) {
        float c = 0.f;
#pragma unroll
        for (int d = 0; d < 8; d++)
            c += g_cnt2[base + (((d >> 2) & 1) << 12) + (((d >> 1) & 1) << 6) + (d & 1)];
        g_cnt4[s4] = c;
    }
}

__global__ __launch_bounds__(256) void reduce8_kernel() {
    int t = blockIdx.x * 256 + threadIdx.x;   // NSEG8 * 16 tasks
    int kc = t & 15;
    int s8 = t >> 4;
    int b = s8 >> 12, x = (s8 >> 8) & 15, y = (s8 >> 4) & 15, z = s8 & 15;
    int base = (b << 15) | ((x << 1) << 10) | ((y << 1) << 5) | (z << 1);
    float4 acc = make_float4(0.f, 0.f, 0.f, 0.f);
#pragma unroll
    for (int d = 0; d < 8; d++) {
        int s4 = base + (((d >> 2) & 1) << 10) + (((d >> 1) & 1) << 5) + (d & 1);
        float4 v = *(const float4*)&g_sums4[(long)s4 * 64 + kc * 4];
        acc.x += v.x; acc.y += v.y; acc.z += v.z; acc.w += v.w;
    }
    *(float4*)&g_sums8[(long)s8 * 64 + kc * 4] = acc;
    if (kc == 0) {
        float c = 0.f;
#pragma unroll
        for (int d = 0; d < 8; d++)
            c += g_cnt4[base + (((d >> 2) & 1) << 10) + (((d >> 1) & 1) << 5) + (d & 1)];
        g_cnt8[s8] = c;
    }
}

// ---------------- kernel 3: level-0 reduce + base projection ----------------
__global__ __launch_bounds__(256) void l0_kernel(
    const float* __restrict__ W, const float* __restrict__ bias)
{
    int b = blockIdx.x;
    int tid = threadIdx.x;
    __shared__ float sm[4][64];
    __shared__ float smean[64];
    __shared__ float scnt[256];

    int c = tid & 63, g = tid >> 6;
    const float* base = g_sums8 + (long)b * 4096 * 64;
    float acc = 0.f;
    for (int s = g; s < 4096; s += 4) acc += base[s * 64 + c];
    sm[g][c] = acc;

    float ca = 0.f;
    for (int s = tid; s < 4096; s += 256) ca += g_cnt8[b * 4096 + s];
    scnt[tid] = ca;
    __syncthreads();

    for (int off = 128; off > 0; off >>= 1) {
        if (tid < off) scnt[tid] += scnt[tid + off];
        __syncthreads();
    }
    if (tid < 64) {
        smean[tid] = (sm[0][tid] + sm[1][tid] + sm[2][tid] + sm[3][tid])
                   / fmaxf(scnt[0], 1.0f);
    }
    __syncthreads();
    if (tid < 96) {
        float a = bias[tid];
        const float* wr = W + tid * 256;  // global block = cols [0,64)
#pragma unroll 8
        for (int k = 0; k < 64; k++) a += wr[k] * smean[k];
        g_base0[b * COUT + tid] = a;
    }
}

// ---------------- shared HMMA tile machinery ----------------
#define A_STRIDE 72   // halves per A row, padded
#define B_U32    36   // uint32 per B row (padded)
#define TILE_PTS 128  // points/segments per block
#define TTHREADS 256  // threads per block (8 warps)

#define SMEM_AH_OFF 0
#define SMEM_AL_OFF (TILE_PTS * A_STRIDE * 2)
#define SMEM_BH_OFF (2 * TILE_PTS * A_STRIDE * 2)
#define SMEM_BL_OFF (SMEM_BH_OFF + 96 * B_U32 * 4)
#define SMEM_DYN    (SMEM_BL_OFF + 96 * B_U32 * 4)

// stage pre-split W level block into smem (conflict-free layout)
__device__ __forceinline__ void stage_W(uint32_t* shBh, uint32_t* shBl,
                                        const uint32_t* __restrict__ Wh,
                                        const uint32_t* __restrict__ Wl,
                                        int tid)
{
    for (int idx = tid; idx < 3072; idx += TTHREADS) {
        int o = idx >> 5, j = idx & 31;
        shBh[o * B_U32 + j] = Wh[idx];
        shBl[o * B_U32 + j] = Wl[idx];
    }
}

// core bf16x3 MMA over staged A (TILE_PTS rows) and W (96 rows), per-warp m16 x n96
__device__ __forceinline__ void mma_tile(
    const __nv_bfloat16* shAh, const __nv_bfloat16* shAl,
    const uint32_t* shBh, const uint32_t* shBl,
    int warp_m, int grp, int qid, float acc[12][4])
{
#pragma unroll
    for (int ks = 0; ks < 4; ks++) {
        int k0 = ks * 16 + qid * 2;
        int ra = (warp_m + grp) * A_STRIDE;
        int rb = (warp_m + grp + 8) * A_STRIDE;
        uint32_t ah0 = *(const uint32_t*)&shAh[ra + k0];
        uint32_t ah1 = *(const uint32_t*)&shAh[rb + k0];
        uint32_t ah2 = *(const uint32_t*)&shAh[ra + k0 + 8];
        uint32_t ah3 = *(const uint32_t*)&shAh[rb + k0 + 8];
        uint32_t al0 = *(const uint32_t*)&shAl[ra + k0];
        uint32_t al1 = *(const uint32_t*)&shAl[rb + k0];
        uint32_t al2 = *(const uint32_t*)&shAl[ra + k0 + 8];
        uint32_t al3 = *(const uint32_t*)&shAl[rb + k0 + 8];
        int wb = ks * 8 + qid;
#pragma unroll
        for (int t = 0; t < 12; t++) {
            int n = t * 8 + grp;
            uint32_t bh0 = shBh[n * B_U32 + wb];
            uint32_t bh1 = shBh[n * B_U32 + wb + 4];
            uint32_t bl0 = shBl[n * B_U32 + wb];
            uint32_t bl1 = shBl[n * B_U32 + wb + 4];
            hmma16816(acc[t][0], acc[t][1], acc[t][2], acc[t][3],
                      ah0, ah1, ah2, ah3, bh0, bh1);
            hmma16816(acc[t][0], acc[t][1], acc[t][2], acc[t][3],
                      ah0, ah1, ah2, ah3, bl0, bl1);
            hmma16816(acc[t][0], acc[t][1], acc[t][2], acc[t][3],
                      al0, al1, al2, al3, bh0, bh1);
        }
    }
}

// ---------------- HMMA transform for levels 8 and 4 (bf16x3) ----------------
template <int LEVEL>
__global__ __launch_bounds__(TTHREADS) void transform_hmma_kernel()
{
    extern __shared__ __align__(16) char dynsmem[];
    __nv_bfloat16* sh_Ah = (__nv_bfloat16*)(dynsmem + SMEM_AH_OFF);
    __nv_bfloat16* sh_Al = (__nv_bfloat16*)(dynsmem + SMEM_AL_OFF);
    uint32_t* sh_Bh = (uint32_t*)(dynsmem + SMEM_BH_OFF);
    uint32_t* sh_Bl = (uint32_t*)(dynsmem + SMEM_BL_OFF);

    int tid  = threadIdx.x;
    int wid  = tid >> 5;
    int lane = tid & 31;
    int base = blockIdx.x * TILE_PTS;

    const float* SUMS = (LEVEL == 4) ? g_sums4 : g_sums8;
    const float* CNT  = (LEVEL == 4) ? g_cnt4  : g_cnt8;
    const int LIDX = (LEVEL == 4) ? 1 : 2;

    stage_W(sh_Bh, sh_Bl, g_Wh32 + LIDX * 3072, g_Wl32 + LIDX * 3072, tid);

    for (int it = tid; it < TILE_PTS * 16; it += TTHREADS) {
        int slot = it >> 4, kc = it & 15;
        int s = base + slot;
        float inv = 1.0f / fmaxf(CNT[s], 1.0f);
        float4 v = *(const float4*)&SUMS[(long)s * 64 + kc * 4];
        uint32_t h0, l0, h1, l1;
        split2(v.x * inv, v.y * inv, h0, l0);
        split2(v.z * inv, v.w * inv, h1, l1);
        uint32_t* dh = (uint32_t*)&sh_Ah[slot * A_STRIDE + kc * 4];
        uint32_t* dl = (uint32_t*)&sh_Al[slot * A_STRIDE + kc * 4];
        dh[0] = h0; dh[1] = h1;
        dl[0] = l0; dl[1] = l1;
    }
    __syncthreads();

    int warp_m = wid * 16;
    int grp = lane >> 2;
    int qid = lane & 3;

    float acc[12][4];
#pragma unroll
    for (int t = 0; t < 12; t++)
#pragma unroll
        for (int j = 0; j < 4; j++) acc[t][j] = 0.f;

    mma_tile(sh_Ah, sh_Al, sh_Bh, sh_Bl, warp_m, grp, qid, acc);

    // epilogue
    int slot0 = warp_m + grp;
    int slot1 = slot0 + 8;
    int s0 = base + slot0;
    int s1 = base + slot1;

    const float* p0;
    const float* p1;
    float* zout;
    if (LEVEL == 8) {
        p0 = &g_base0[(s0 >> 12) * COUT];
        p1 = &g_base0[(s1 >> 12) * COUT];
        zout = g_Z8;
    } else {
        int bb0 = s0 >> 15, xx0 = (s0 >> 10) & 31, yy0 = (s0 >> 5) & 31, zz0 = s0 & 31;
        int bb1 = s1 >> 15, xx1 = (s1 >> 10) & 31, yy1 = (s1 >> 5) & 31, zz1 = s1 & 31;
        p0 = &g_Z8[(long)((bb0 << 12) | ((xx0 >> 1) << 8) | ((yy0 >> 1) << 4) | (zz0 >> 1)) * COUT];
        p1 = &g_Z8[(long)((bb1 << 12) | ((xx1 >> 1) << 8) | ((yy1 >> 1) << 4) | (zz1 >> 1)) * COUT];
        zout = g_Z4;
    }
    float* d0 = zout + (long)s0 * COUT;
    float* d1 = zout + (long)s1 * COUT;

#pragma unroll
    for (int t = 0; t < 12; t++) {
        int c = t * 8 + qid * 2;
        float2 za = *(const float2*)&p0[c];
        float2 zb = *(const float2*)&p1[c];
        *(float2*)&d0[c] = make_float2(acc[t][0] + za.x, acc[t][1] + za.y);
        *(float2*)&d1[c] = make_float2(acc[t][2] + zb.x, acc[t][3] + zb.y);
    }
}

// ---------------- fused level-2 transform + output (bf16x3 HMMA) ----------------
__global__ __launch_bounds__(TTHREADS) void fused_mma_kernel(float* __restrict__ out)
{
    extern __shared__ __align__(16) char dynsmem[];
    __nv_bfloat16* sh_Ah = (__nv_bfloat16*)(dynsmem + SMEM_AH_OFF);
    __nv_bfloat16* sh_Al = (__nv_bfloat16*)(dynsmem + SMEM_AL_OFF);
    uint32_t* sh_Bh = (uint32_t*)(dynsmem + SMEM_BH_OFF);
    uint32_t* sh_Bl = (uint32_t*)(dynsmem + SMEM_BL_OFF);

    __shared__ int   s_s4[TILE_PTS];
    __shared__ int   s_sid[TILE_PTS];
    __shared__ float s_inv[TILE_PTS];

    int tid  = threadIdx.x;
    int wid  = tid >> 5;
    int lane = tid & 31;
    int pbase = blockIdx.x * TILE_PTS;

    if (tid < TILE_PTS) {
        int s2 = g_seg2[pbase + tid];
        s_sid[tid] = s2;
        int bb = s2 >> 18, xx = (s2 >> 12) & 63, yy = (s2 >> 6) & 63, zz = s2 & 63;
        s_s4[tid] = (bb << 15) | ((xx >> 1) << 10) | ((yy >> 1) << 5) | (zz >> 1);
        s_inv[tid] = 1.0f / fmaxf(g_cnt2[s2], 1.0f);
    }

    stage_W(sh_Bh, sh_Bl, g_Wh32, g_Wl32, tid);   // level-2 block (LIDX 0)
    __syncthreads();

    // stage A: TILE_PTS mean rows -> bf16 hi/lo
    for (int it = tid; it < TILE_PTS * 16; it += TTHREADS) {
        int slot = it >> 4, kc = it & 15;
        int s = s_sid[slot];
        float inv = s_inv[slot];
        float4 v = *(const float4*)&g_sums2[(long)s * 64 + kc * 4];
        uint32_t h0, l0, h1, l1;
        split2(v.x * inv, v.y * inv, h0, l0);
        split2(v.z * inv, v.w * inv, h1, l1);
        uint32_t* dh = (uint32_t*)&sh_Ah[slot * A_STRIDE + kc * 4];
        uint32_t* dl = (uint32_t*)&sh_Al[slot * A_STRIDE + kc * 4];
        dh[0] = h0; dh[1] = h1;
        dl[0] = l0; dl[1] = l1;
    }
    __syncthreads();

    int warp_m = wid * 16;
    int grp = lane >> 2;
    int qid = lane & 3;

    float acc[12][4];
#pragma unroll
    for (int t = 0; t < 12; t++)
#pragma unroll
        for (int j = 0; j < 4; j++) acc[t][j] = 0.f;

    mma_tile(sh_Ah, sh_Al, sh_Bh, sh_Bl, warp_m, grp, qid, acc);

    // epilogue: out[p] = Z4[s4(p)] + D[p]
    int slot0 = warp_m + grp;
    int slot1 = slot0 + 8;
    const float* z0 = &g_Z4[(long)s_s4[slot0] * COUT];
    const float* z1 = &g_Z4[(long)s_s4[slot1] * COUT];
    float* d0 = out + (long)(pbase + slot0) * COUT;
    float* d1 = out + (long)(pbase + slot1) * COUT;

#pragma unroll
    for (int t = 0; t < 12; t++) {
        int c = t * 8 + qid * 2;
        float2 za = *(const float2*)&z0[c];
        float2 zb = *(const float2*)&z1[c];
        *(float2*)&d0[c] = make_float2(acc[t][0] + za.x, acc[t][1] + za.y);
        *(float2*)&d1[c] = make_float2(acc[t][2] + zb.x, acc[t][3] + zb.y);
    }
}

// ---------------- launcher ----------------
extern "C" void kernel_launch(void* const* d_in, const int* in_sizes, int n_in,
                              void* d_out, int out_size)
{
    const float* feats  = (const float*)d_in[0];
    const int*   coords = (const int*)d_in[1];
    const int*   batch  = (const int*)d_in[2];
    const float* W      = (const float*)d_in[3];
    const float* bias   = (const float*)d_in[4];

    // opt into >48KB dynamic smem (attribute set, not an allocation; idempotent)
    static bool attr_done = false;
    if (!attr_done) {
        cudaFuncSetAttribute(fused_mma_kernel,
                             cudaFuncAttributeMaxDynamicSharedMemorySize, SMEM_DYN);
        cudaFuncSetAttribute(transform_hmma_kernel<4>,
                             cudaFuncAttributeMaxDynamicSharedMemorySize, SMEM_DYN);
        cudaFuncSetAttribute(transform_hmma_kernel<8>,
                             cudaFuncAttributeMaxDynamicSharedMemorySize, SMEM_DYN);
        attr_done = true;
    }

    zero_sums_kernel<<<2048, 256>>>();      // launch 1
    zero_cnt_kernel<<<256, 256>>>();        // launch 2
    split_w_kernel<<<36, 256>>>(W);         // launch 3
    scatter_kernel<<<8192, 256>>>((const float4*)feats, coords, batch);  // launch 4 (profiled)
    reduce4_kernel<<<(NSEG4 * 16) / 256, 256>>>();
    reduce8_kernel<<<(NSEG8 * 16) / 256, 256>>>();
    l0_kernel<<<NB, 256>>>(W, bias);
    transform_hmma_kernel<8><<<NSEG8 / TILE_PTS, TTHREADS, SMEM_DYN>>>();
    transform_hmma_kernel<4><<<NSEG4 / TILE_PTS, TTHREADS, SMEM_DYN>>>();
    fused_mma_kernel<<<NPTS / TILE_PTS, TTHREADS, SMEM_DYN>>>((float*)d_out);
}

// round 12
// speedup vs baseline: 1.2118x; 1.0478x over previous
#include <cuda_runtime.h>
#include <cuda_bf16.h>
#include <cstdint>

// Problem constants
#define NPTS   1048576
#define CIN    64
#define COUT   96
#define NB     4
#define NSEG2  1048576   // 4 * 64^3
#define NSEG4  131072    // 4 * 32^3
#define NSEG8  16384     // 4 * 16^3

// ---------------- static device scratch ----------------
__device__ float g_sums2[(long)NSEG2 * 64];   // 268 MB
__device__ float g_cnt2[NSEG2];
__device__ float g_sums4[(long)NSEG4 * 64];   // 33.5 MB
__device__ float g_cnt4[NSEG4];
__device__ float g_sums8[(long)NSEG8 * 64];   // 4 MB
__device__ float g_cnt8[NSEG8];
__device__ float g_base0[NB * COUT];
__device__ float g_Z8[(long)NSEG8 * COUT];    // 6.3 MB
__device__ float g_Z4[(long)NSEG4 * COUT];    // 50 MB
__device__ int   g_seg2[NPTS];
// pre-split W blocks (levels 2,4,8), packed bf16x2: [L][o][j], j = k/2
__device__ uint32_t g_Wh32[3 * 96 * 32];
__device__ uint32_t g_Wl32[3 * 96 * 32];
// l0 partials
__device__ float g_l0part[64 * 64];
__device__ float g_l0cnt[64];

// ---------------- PTX helpers ----------------
__device__ __forceinline__ void red_add_v4(float* addr, float4 v) {
    asm volatile("red.global.add.v4.f32 [%0], {%1, %2, %3, %4};"
                 :: "l"(addr), "f"(v.x), "f"(v.y), "f"(v.z), "f"(v.w)
                 : "memory");
}

__device__ __forceinline__ void hmma16816(
    float& c0, float& c1, float& c2, float& c3,
    uint32_t a0, uint32_t a1, uint32_t a2, uint32_t a3,
    uint32_t b0, uint32_t b1)
{
    asm volatile(
        "mma.sync.aligned.m16n8k16.row.col.f32.bf16.bf16.f32 "
        "{%0,%1,%2,%3}, {%4,%5,%6,%7}, {%8,%9}, {%0,%1,%2,%3};"
        : "+f"(c0), "+f"(c1), "+f"(c2), "+f"(c3)
        : "r"(a0), "r"(a1), "r"(a2), "r"(a3), "r"(b0), "r"(b1));
}

// split float pair into (hi bf16x2, lo bf16x2)
__device__ __forceinline__ void split2(float x, float y, uint32_t& hi, uint32_t& lo) {
    __nv_bfloat16 hx = __float2bfloat16_rn(x);
    __nv_bfloat16 hy = __float2bfloat16_rn(y);
    __nv_bfloat16 lx = __float2bfloat16_rn(x - __bfloat162float(hx));
    __nv_bfloat16 ly = __float2bfloat16_rn(y - __bfloat162float(hy));
    __nv_bfloat162 h = {hx, hy};
    __nv_bfloat162 l = {lx, ly};
    hi = *(uint32_t*)&h;
    lo = *(uint32_t*)&l;
}

// ---------------- kernel 1a/1b: zero scratch ----------------
__global__ void zero_sums_kernel() {
    long tid = (long)blockIdx.x * blockDim.x + threadIdx.x;
    long stride = (long)gridDim.x * blockDim.x;
    float4 z = make_float4(0.f, 0.f, 0.f, 0.f);
    float4* s2 = (float4*)g_sums2;
    for (long i = tid; i < (long)NSEG2 * 16; i += stride) s2[i] = z;
}
__global__ void zero_cnt_kernel() {
    long tid = (long)blockIdx.x * blockDim.x + threadIdx.x;
    long stride = (long)gridDim.x * blockDim.x;
    float4 z = make_float4(0.f, 0.f, 0.f, 0.f);
    float4* c2 = (float4*)g_cnt2;
    for (long i = tid; i < NSEG2 / 4; i += stride) c2[i] = z;
}

// ---------------- kernel 0: pre-split W into bf16 hi/lo tables ----------------
__global__ __launch_bounds__(256) void split_w_kernel(const float* __restrict__ W) {
    int idx = blockIdx.x * 256 + threadIdx.x;   // 3*96*32 = 9216
    if (idx >= 9216) return;
    int L = idx / 3072;
    int r = idx - L * 3072;
    int o = r >> 5, j = r & 31;
    const float* src = W + o * 256 + 64 + L * 64 + 2 * j;
    uint32_t h, l;
    split2(src[0], src[1], h, l);
    g_Wh32[idx] = h;
    g_Wl32[idx] = l;
}

// ---------------- kernel 2: chunk-parallel scatter into level-2 ----------------
__global__ __launch_bounds__(256) void scatter_kernel(
    const float4* __restrict__ feats4,
    const int* __restrict__ coords,
    const int* __restrict__ batch)
{
    const long TOTAL = (long)NPTS * 16;
    long stride = (long)gridDim.x * blockDim.x;
    for (long idx = (long)blockIdx.x * blockDim.x + threadIdx.x; idx < TOTAL; idx += stride) {
        int p  = (int)(idx >> 4);
        int kc = (int)(idx & 15);
        int x = coords[3 * p + 0];
        int y = coords[3 * p + 1];
        int z = coords[3 * p + 2];
        int b = batch[p];
        int s2 = (b << 18) | ((x >> 1) << 12) | ((y >> 1) << 6) | (z >> 1);
        if (kc == 0) {
            g_seg2[p] = s2;
            atomicAdd(&g_cnt2[s2], 1.0f);
        }
        float4 v = feats4[(long)p * 16 + kc];
        red_add_v4(&g_sums2[(long)s2 * 64 + kc * 4], v);
    }
}

// ---------------- kernel 2b: hierarchical reductions ----------------
__global__ __launch_bounds__(256) void reduce4_kernel() {
    int t = blockIdx.x * 256 + threadIdx.x;   // NSEG4 * 16 tasks
    int kc = t & 15;
    int s4 = t >> 4;
    int b = s4 >> 15, x = (s4 >> 10) & 31, y = (s4 >> 5) & 31, z = s4 & 31;
    int base = (b << 18) | ((x << 1) << 12) | ((y << 1) << 6) | (z << 1);
    float4 acc = make_float4(0.f, 0.f, 0.f, 0.f);
#pragma unroll
    for (int d = 0; d < 8; d++) {
        int s2 = base + (((d >> 2) & 1) << 12) + (((d >> 1) & 1) << 6) + (d & 1);
        float4 v = *(const float4*)&g_sums2[(long)s2 * 64 + kc * 4];
        acc.x += v.x; acc.y += v.y; acc.z += v.z; acc.w += v.w;
    }
    *(float4*)&g_sums4[(long)s4 * 64 + kc * 4] = acc;
    if (kc == 0) {
        float c = 0.f;
#pragma unroll
        for (int d = 0; d < 8; d++)
            c += g_cnt2[base + (((d >> 2) & 1) << 12) + (((d >> 1) & 1) << 6) + (d & 1)];
        g_cnt4[s4] = c;
    }
}

__global__ __launch_bounds__(256) void reduce8_kernel() {
    int t = blockIdx.x * 256 + threadIdx.x;   // NSEG8 * 16 tasks
    int kc = t & 15;
    int s8 = t >> 4;
    int b = s8 >> 12, x = (s8 >> 8) & 15, y = (s8 >> 4) & 15, z = s8 & 15;
    int base = (b << 15) | ((x << 1) << 10) | ((y << 1) << 5) | (z << 1);
    float4 acc = make_float4(0.f, 0.f, 0.f, 0.f);
#pragma unroll
    for (int d = 0; d < 8; d++) {
        int s4 = base + (((d >> 2) & 1) << 10) + (((d >> 1) & 1) << 5) + (d & 1);
        float4 v = *(const float4*)&g_sums4[(long)s4 * 64 + kc * 4];
        acc.x += v.x; acc.y += v.y; acc.z += v.z; acc.w += v.w;
    }
    *(float4*)&g_sums8[(long)s8 * 64 + kc * 4] = acc;
    if (kc == 0) {
        float c = 0.f;
#pragma unroll
        for (int d = 0; d < 8; d++)
            c += g_cnt4[base + (((d >> 2) & 1) << 10) + (((d >> 1) & 1) << 5) + (d & 1)];
        g_cnt8[s8] = c;
    }
}

// ---------------- kernel 3a: l0 partial reduce (64 blocks) ----------------
__global__ __launch_bounds__(256) void l0_part_kernel() {
    int blk = blockIdx.x;           // 0..63
    int b = blk >> 4, part = blk & 15;
    int tid = threadIdx.x;
    __shared__ float sm[4][64];
    __shared__ float scnt[256];

    int c = tid & 63, g = tid >> 6;
    int row0 = b * 4096 + part * 256;
    const float* base = g_sums8 + (long)row0 * 64;
    float acc = 0.f;
    for (int s = g; s < 256; s += 4) acc += base[s * 64 + c];
    sm[g][c] = acc;

    float ca = 0.f;
    for (int s = tid; s < 256; s += 256) ca += g_cnt8[row0 + s];
    scnt[tid] = ca;
    __syncthreads();

    for (int off = 128; off > 0; off >>= 1) {
        if (tid < off) scnt[tid] += scnt[tid + off];
        __syncthreads();
    }
    if (tid < 64)
        g_l0part[blk * 64 + tid] = sm[0][tid] + sm[1][tid] + sm[2][tid] + sm[3][tid];
    if (tid == 0)
        g_l0cnt[blk] = scnt[0];
}

// ---------------- kernel 3b: l0 final projection (4 blocks) ----------------
__global__ __launch_bounds__(128) void l0_final_kernel(
    const float* __restrict__ W, const float* __restrict__ bias)
{
    int b = blockIdx.x;
    int tid = threadIdx.x;
    __shared__ float smean[64];
    __shared__ float scnt_sh;

    if (tid < 64) {
        float s = 0.f;
#pragma unroll
        for (int k = 0; k < 16; k++) s += g_l0part[(b * 16 + k) * 64 + tid];
        smean[tid] = s;
    }
    if (tid == 0) {
        float c = 0.f;
#pragma unroll
        for (int k = 0; k < 16; k++) c += g_l0cnt[b * 16 + k];
        scnt_sh = fmaxf(c, 1.0f);
    }
    __syncthreads();
    if (tid < 64) smean[tid] /= scnt_sh;
    __syncthreads();
    if (tid < 96) {
        float a = bias[tid];
        const float* wr = W + tid * 256;  // global block = cols [0,64)
#pragma unroll 8
        for (int k = 0; k < 64; k++) a += wr[k] * smean[k];
        g_base0[b * COUT + tid] = a;
    }
}

// ---------------- shared HMMA tile machinery ----------------
#define A_STRIDE 72   // halves per A row, padded
#define B_U32    36   // uint32 per B row (padded)
#define TILE_PTS 128  // points/segments per block
#define TTHREADS 256  // threads per block (8 warps)
#define D_STRIDE 100  // floats per D row in smem (400B, 16B-aligned)

#define SMEM_AH_OFF 0
#define SMEM_AL_OFF (TILE_PTS * A_STRIDE * 2)
#define SMEM_BH_OFF (2 * TILE_PTS * A_STRIDE * 2)
#define SMEM_BL_OFF (SMEM_BH_OFF + 96 * B_U32 * 4)
#define SMEM_DYN    (SMEM_BL_OFF + 96 * B_U32 * 4)
// D tile (reuses A/B region after MMA): TILE_PTS * D_STRIDE * 4 = 51200 <= SMEM_DYN

// stage pre-split W level block into smem (conflict-free layout)
__device__ __forceinline__ void stage_W(uint32_t* shBh, uint32_t* shBl,
                                        const uint32_t* __restrict__ Wh,
                                        const uint32_t* __restrict__ Wl,
                                        int tid)
{
    for (int idx = tid; idx < 3072; idx += TTHREADS) {
        int o = idx >> 5, j = idx & 31;
        shBh[o * B_U32 + j] = Wh[idx];
        shBl[o * B_U32 + j] = Wl[idx];
    }
}

// core bf16x3 MMA over staged A (TILE_PTS rows) and W (96 rows), per-warp m16 x n96
__device__ __forceinline__ void mma_tile(
    const __nv_bfloat16* shAh, const __nv_bfloat16* shAl,
    const uint32_t* shBh, const uint32_t* shBl,
    int warp_m, int grp, int qid, float acc[12][4])
{
#pragma unroll
    for (int ks = 0; ks < 4; ks++) {
        int k0 = ks * 16 + qid * 2;
        int ra = (warp_m + grp) * A_STRIDE;
        int rb = (warp_m + grp + 8) * A_STRIDE;
        uint32_t ah0 = *(const uint32_t*)&shAh[ra + k0];
        uint32_t ah1 = *(const uint32_t*)&shAh[rb + k0];
        uint32_t ah2 = *(const uint32_t*)&shAh[ra + k0 + 8];
        uint32_t ah3 = *(const uint32_t*)&shAh[rb + k0 + 8];
        uint32_t al0 = *(const uint32_t*)&shAl[ra + k0];
        uint32_t al1 = *(const uint32_t*)&shAl[rb + k0];
        uint32_t al2 = *(const uint32_t*)&shAl[ra + k0 + 8];
        uint32_t al3 = *(const uint32_t*)&shAl[rb + k0 + 8];
        int wb = ks * 8 + qid;
#pragma unroll
        for (int t = 0; t < 12; t++) {
            int n = t * 8 + grp;
            uint32_t bh0 = shBh[n * B_U32 + wb];
            uint32_t bh1 = shBh[n * B_U32 + wb + 4];
            uint32_t bl0 = shBl[n * B_U32 + wb];
            uint32_t bl1 = shBl[n * B_U32 + wb + 4];
            hmma16816(acc[t][0], acc[t][1], acc[t][2], acc[t][3],
                      ah0, ah1, ah2, ah3, bh0, bh1);
            hmma16816(acc[t][0], acc[t][1], acc[t][2], acc[t][3],
                      ah0, ah1, ah2, ah3, bl0, bl1);
            hmma16816(acc[t][0], acc[t][1], acc[t][2], acc[t][3],
                      al0, al1, al2, al3, bh0, bh1);
        }
    }
}

// ---------------- HMMA transform for levels 8 and 4 (bf16x3) ----------------
template <int LEVEL>
__global__ __launch_bounds__(TTHREADS) void transform_hmma_kernel()
{
    extern __shared__ __align__(16) char dynsmem[];
    __nv_bfloat16* sh_Ah = (__nv_bfloat16*)(dynsmem + SMEM_AH_OFF);
    __nv_bfloat16* sh_Al = (__nv_bfloat16*)(dynsmem + SMEM_AL_OFF);
    uint32_t* sh_Bh = (uint32_t*)(dynsmem + SMEM_BH_OFF);
    uint32_t* sh_Bl = (uint32_t*)(dynsmem + SMEM_BL_OFF);

    int tid  = threadIdx.x;
    int wid  = tid >> 5;
    int lane = tid & 31;
    int base = blockIdx.x * TILE_PTS;

    const float* SUMS = (LEVEL == 4) ? g_sums4 : g_sums8;
    const float* CNT  = (LEVEL == 4) ? g_cnt4  : g_cnt8;
    const int LIDX = (LEVEL == 4) ? 1 : 2;

    stage_W(sh_Bh, sh_Bl, g_Wh32 + LIDX * 3072, g_Wl32 + LIDX * 3072, tid);

    for (int it = tid; it < TILE_PTS * 16; it += TTHREADS) {
        int slot = it >> 4, kc = it & 15;
        int s = base + slot;
        float inv = 1.0f / fmaxf(CNT[s], 1.0f);
        float4 v = *(const float4*)&SUMS[(long)s * 64 + kc * 4];
        uint32_t h0, l0, h1, l1;
        split2(v.x * inv, v.y * inv, h0, l0);
        split2(v.z * inv, v.w * inv, h1, l1);
        uint32_t* dh = (uint32_t*)&sh_Ah[slot * A_STRIDE + kc * 4];
        uint32_t* dl = (uint32_t*)&sh_Al[slot * A_STRIDE + kc * 4];
        dh[0] = h0; dh[1] = h1;
        dl[0] = l0; dl[1] = l1;
    }
    __syncthreads();

    int warp_m = wid * 16;
    int grp = lane >> 2;
    int qid = lane & 3;

    float acc[12][4];
#pragma unroll
    for (int t = 0; t < 12; t++)
#pragma unroll
        for (int j = 0; j < 4; j++) acc[t][j] = 0.f;

    mma_tile(sh_Ah, sh_Al, sh_Bh, sh_Bl, warp_m, grp, qid, acc);

    // epilogue
    int slot0 = warp_m + grp;
    int slot1 = slot0 + 8;
    int s0 = base + slot0;
    int s1 = base + slot1;

    const float* p0;
    const float* p1;
    float* zout;
    if (LEVEL == 8) {
        p0 = &g_base0[(s0 >> 12) * COUT];
        p1 = &g_base0[(s1 >> 12) * COUT];
        zout = g_Z8;
    } else {
        int bb0 = s0 >> 15, xx0 = (s0 >> 10) & 31, yy0 = (s0 >> 5) & 31, zz0 = s0 & 31;
        int bb1 = s1 >> 15, xx1 = (s1 >> 10) & 31, yy1 = (s1 >> 5) & 31, zz1 = s1 & 31;
        p0 = &g_Z8[(long)((bb0 << 12) | ((xx0 >> 1) << 8) | ((yy0 >> 1) << 4) | (zz0 >> 1)) * COUT];
        p1 = &g_Z8[(long)((bb1 << 12) | ((xx1 >> 1) << 8) | ((yy1 >> 1) << 4) | (zz1 >> 1)) * COUT];
        zout = g_Z4;
    }
    float* d0 = zout + (long)s0 * COUT;
    float* d1 = zout + (long)s1 * COUT;

#pragma unroll
    for (int t = 0; t < 12; t++) {
        int c = t * 8 + qid * 2;
        float2 za = *(const float2*)&p0[c];
        float2 zb = *(const float2*)&p1[c];
        *(float2*)&d0[c] = make_float2(acc[t][0] + za.x, acc[t][1] + za.y);
        *(float2*)&d1[c] = make_float2(acc[t][2] + zb.x, acc[t][3] + zb.y);
    }
}

// ---------------- fused level-2 transform + output (bf16x3 HMMA) ----------------
__global__ __launch_bounds__(TTHREADS) void fused_mma_kernel(float* __restrict__ out)
{
    extern __shared__ __align__(16) char dynsmem[];
    __nv_bfloat16* sh_Ah = (__nv_bfloat16*)(dynsmem + SMEM_AH_OFF);
    __nv_bfloat16* sh_Al = (__nv_bfloat16*)(dynsmem + SMEM_AL_OFF);
    uint32_t* sh_Bh = (uint32_t*)(dynsmem + SMEM_BH_OFF);
    uint32_t* sh_Bl = (uint32_t*)(dynsmem + SMEM_BL_OFF);

    __shared__ int   s_s4[TILE_PTS];
    __shared__ int   s_sid[TILE_PTS];
    __shared__ float s_inv[TILE_PTS];

    int tid  = threadIdx.x;
    int wid  = tid >> 5;
    int lane = tid & 31;
    int pbase = blockIdx.x * TILE_PTS;

    if (tid < TILE_PTS) {
        int s2 = g_seg2[pbase + tid];
        s_sid[tid] = s2;
        int bb = s2 >> 18, xx = (s2 >> 12) & 63, yy = (s2 >> 6) & 63, zz = s2 & 63;
        s_s4[tid] = (bb << 15) | ((xx >> 1) << 10) | ((yy >> 1) << 5) | (zz >> 1);
        s_inv[tid] = 1.0f / fmaxf(g_cnt2[s2], 1.0f);
    }

    stage_W(sh_Bh, sh_Bl, g_Wh32, g_Wl32, tid);   // level-2 block (LIDX 0)
    __syncthreads();

    // stage A: TILE_PTS mean rows -> bf16 hi/lo
    for (int it = tid; it < TILE_PTS * 16; it += TTHREADS) {
        int slot = it >> 4, kc = it & 15;
        int s = s_sid[slot];
        float inv = s_inv[slot];
        float4 v = *(const float4*)&g_sums2[(long)s * 64 + kc * 4];
        uint32_t h0, l0, h1, l1;
        split2(v.x * inv, v.y * inv, h0, l0);
        split2(v.z * inv, v.w * inv, h1, l1);
        uint32_t* dh = (uint32_t*)&sh_Ah[slot * A_STRIDE + kc * 4];
        uint32_t* dl = (uint32_t*)&sh_Al[slot * A_STRIDE + kc * 4];
        dh[0] = h0; dh[1] = h1;
        dl[0] = l0; dl[1] = l1;
    }
    __syncthreads();

    int warp_m = wid * 16;
    int grp = lane >> 2;
    int qid = lane & 3;

    float acc[12][4];
#pragma unroll
    for (int t = 0; t < 12; t++)
#pragma unroll
        for (int j = 0; j < 4; j++) acc[t][j] = 0.f;

    mma_tile(sh_Ah, sh_Al, sh_Bh, sh_Bl, warp_m, grp, qid, acc);

    // ---- coalesced epilogue: stage D in smem (reusing A/B region), then
    //      stream Z4-add + out write with coalesced float4 accesses ----
    __syncthreads();   // all smem A/B reads done; safe to overwrite
    float* sh_D = (float*)dynsmem;
    {
        int r0 = warp_m + grp, r1 = r0 + 8;
#pragma unroll
        for (int t = 0; t < 12; t++) {
            int c = t * 8 + qid * 2;
            *(float2*)&sh_D[r0 * D_STRIDE + c] = make_float2(acc[t][0], acc[t][1]);
            *(float2*)&sh_D[r1 * D_STRIDE + c] = make_float2(acc[t][2], acc[t][3]);
        }
    }
    __syncthreads();

    for (int it = tid; it < TILE_PTS * 24; it += TTHREADS) {
        int slot = it / 24;
        int ch = it - slot * 24;
        float4 d = *(const float4*)&sh_D[slot * D_STRIDE + ch * 4];
        float4 z = *(const float4*)&g_Z4[(long)s_s4[slot] * COUT + ch * 4];
        float4 o = make_float4(d.x + z.x, d.y + z.y, d.z + z.z, d.w + z.w);
        *(float4*)&out[(long)(pbase + slot) * COUT + ch * 4] = o;
    }
}

// ---------------- launcher ----------------
extern "C" void kernel_launch(void* const* d_in, const int* in_sizes, int n_in,
                              void* d_out, int out_size)
{
    const float* feats  = (const float*)d_in[0];
    const int*   coords = (const int*)d_in[1];
    const int*   batch  = (const int*)d_in[2];
    const float* W      = (const float*)d_in[3];
    const float* bias   = (const float*)d_in[4];

    // opt into >48KB dynamic smem (attribute set, not an allocation; idempotent)
    static bool attr_done = false;
    if (!attr_done) {
        cudaFuncSetAttribute(fused_mma_kernel,
                             cudaFuncAttributeMaxDynamicSharedMemorySize, SMEM_DYN);
        cudaFuncSetAttribute(transform_hmma_kernel<4>,
                             cudaFuncAttributeMaxDynamicSharedMemorySize, SMEM_DYN);
        cudaFuncSetAttribute(transform_hmma_kernel<8>,
                             cudaFuncAttributeMaxDynamicSharedMemorySize, SMEM_DYN);
        attr_done = true;
    }

    zero_sums_kernel<<<2048, 256>>>();
    zero_cnt_kernel<<<256, 256>>>();
    split_w_kernel<<<36, 256>>>(W);
    scatter_kernel<<<8192, 256>>>((const float4*)feats, coords, batch);
    reduce4_kernel<<<(NSEG4 * 16) / 256, 256>>>();
    reduce8_kernel<<<(NSEG8 * 16) / 256, 256>>>();
    l0_part_kernel<<<64, 256>>>();
    l0_final_kernel<<<NB, 128>>>(W, bias);
    transform_hmma_kernel<8><<<NSEG8 / TILE_PTS, TTHREADS, SMEM_DYN>>>();
    transform_hmma_kernel<4><<<NSEG4 / TILE_PTS, TTHREADS, SMEM_DYN>>>();
    fused_mma_kernel<<<NPTS / TILE_PTS, TTHREADS, SMEM_DYN>>>((float*)d_out);
}

// round 13
// speedup vs baseline: 1.3623x; 1.1242x over previous
#include <cuda_runtime.h>
#include <cuda_bf16.h>
#include <cstdint>

// Problem constants
#define NPTS   1048576
#define CIN    64
#define COUT   96
#define NB     4
#define NSEG2  1048576   // 4 * 64^3
#define NSEG4  131072    // 4 * 32^3
#define NSEG8  16384     // 4 * 16^3

// ---------------- static device scratch ----------------
__device__ float g_sums2[(long)NSEG2 * 64];   // 268 MB
__device__ float g_cnt2[NSEG2];
__device__ float g_sums4[(long)NSEG4 * 64];   // 33.5 MB
__device__ float g_cnt4[NSEG4];
__device__ float g_sums8[(long)NSEG8 * 64];   // 4 MB
__device__ float g_cnt8[NSEG8];
__device__ float g_base0[NB * COUT];
__device__ float g_Z8[(long)NSEG8 * COUT];    // 6.3 MB
__device__ float g_Z4[(long)NSEG4 * COUT];    // 50 MB
__device__ int   g_seg2[NPTS];
// pre-split W blocks (levels 2,4,8), packed bf16x2: [L][o][j], j = k/2
__device__ uint32_t g_Wh32[3 * 96 * 32];
__device__ uint32_t g_Wl32[3 * 96 * 32];
// l0 partials
__device__ float g_l0part[64 * 64];
__device__ float g_l0cnt[64];

// ---------------- PTX helpers ----------------
__device__ __forceinline__ void red_add_v4(float* addr, float4 v) {
    asm volatile("red.global.add.v4.f32 [%0], {%1, %2, %3, %4};"
                 :: "l"(addr), "f"(v.x), "f"(v.y), "f"(v.z), "f"(v.w)
                 : "memory");
}

__device__ __forceinline__ void hmma16816(
    float& c0, float& c1, float& c2, float& c3,
    uint32_t a0, uint32_t a1, uint32_t a2, uint32_t a3,
    uint32_t b0, uint32_t b1)
{
    asm volatile(
        "mma.sync.aligned.m16n8k16.row.col.f32.bf16.bf16.f32 "
        "{%0,%1,%2,%3}, {%4,%5,%6,%7}, {%8,%9}, {%0,%1,%2,%3};"
        : "+f"(c0), "+f"(c1), "+f"(c2), "+f"(c3)
        : "r"(a0), "r"(a1), "r"(a2), "r"(a3), "r"(b0), "r"(b1));
}

// split float pair into (hi bf16x2, lo bf16x2)
__device__ __forceinline__ void split2(float x, float y, uint32_t& hi, uint32_t& lo) {
    __nv_bfloat16 hx = __float2bfloat16_rn(x);
    __nv_bfloat16 hy = __float2bfloat16_rn(y);
    __nv_bfloat16 lx = __float2bfloat16_rn(x - __bfloat162float(hx));
    __nv_bfloat16 ly = __float2bfloat16_rn(y - __bfloat162float(hy));
    __nv_bfloat162 h = {hx, hy};
    __nv_bfloat162 l = {lx, ly};
    hi = *(uint32_t*)&h;
    lo = *(uint32_t*)&l;
}

// ---------------- kernel 1a/1b: zero scratch ----------------
__global__ void zero_sums_kernel() {
    long tid = (long)blockIdx.x * blockDim.x + threadIdx.x;
    long stride = (long)gridDim.x * blockDim.x;
    float4 z = make_float4(0.f, 0.f, 0.f, 0.f);
    float4* s2 = (float4*)g_sums2;
    for (long i = tid; i < (long)NSEG2 * 16; i += stride) s2[i] = z;
}
__global__ void zero_cnt_kernel() {
    long tid = (long)blockIdx.x * blockDim.x + threadIdx.x;
    long stride = (long)gridDim.x * blockDim.x;
    float4 z = make_float4(0.f, 0.f, 0.f, 0.f);
    float4* c2 = (float4*)g_cnt2;
    for (long i = tid; i < NSEG2 / 4; i += stride) c2[i] = z;
}

// ---------------- kernel 0: pre-split W into bf16 hi/lo tables ----------------
__global__ __launch_bounds__(256) void split_w_kernel(const float* __restrict__ W) {
    int idx = blockIdx.x * 256 + threadIdx.x;   // 3*96*32 = 9216
    if (idx >= 9216) return;
    int L = idx / 3072;
    int r = idx - L * 3072;
    int o = r >> 5, j = r & 31;
    const float* src = W + o * 256 + 64 + L * 64 + 2 * j;
    uint32_t h, l;
    split2(src[0], src[1], h, l);
    g_Wh32[idx] = h;
    g_Wl32[idx] = l;
}

// ---------------- kernel 2: chunk-parallel scatter into level-2 ----------------
__global__ __launch_bounds__(256) void scatter_kernel(
    const float4* __restrict__ feats4,
    const int* __restrict__ coords,
    const int* __restrict__ batch)
{
    const long TOTAL = (long)NPTS * 16;
    long stride = (long)gridDim.x * blockDim.x;
    for (long idx = (long)blockIdx.x * blockDim.x + threadIdx.x; idx < TOTAL; idx += stride) {
        int p  = (int)(idx >> 4);
        int kc = (int)(idx & 15);
        int x = coords[3 * p + 0];
        int y = coords[3 * p + 1];
        int z = coords[3 * p + 2];
        int b = batch[p];
        int s2 = (b << 18) | ((x >> 1) << 12) | ((y >> 1) << 6) | (z >> 1);
        if (kc == 0) {
            g_seg2[p] = s2;
            atomicAdd(&g_cnt2[s2], 1.0f);
        }
        float4 v = feats4[(long)p * 16 + kc];
        red_add_v4(&g_sums2[(long)s2 * 64 + kc * 4], v);
    }
}

// ---------------- kernel 2b: hierarchical reductions ----------------
__global__ __launch_bounds__(256) void reduce4_kernel() {
    int t = blockIdx.x * 256 + threadIdx.x;   // NSEG4 * 16 tasks
    int kc = t & 15;
    int s4 = t >> 4;
    int b = s4 >> 15, x = (s4 >> 10) & 31, y = (s4 >> 5) & 31, z = s4 & 31;
    int base = (b << 18) | ((x << 1) << 12) | ((y << 1) << 6) | (z << 1);
    float4 acc = make_float4(0.f, 0.f, 0.f, 0.f);
#pragma unroll
    for (int d = 0; d < 8; d++) {
        int s2 = base + (((d >> 2) & 1) << 12) + (((d >> 1) & 1) << 6) + (d & 1);
        float4 v = *(const float4*)&g_sums2[(long)s2 * 64 + kc * 4];
        acc.x += v.x; acc.y += v.y; acc.z += v.z; acc.w += v.w;
    }
    *(float4*)&g_sums4[(long)s4 * 64 + kc * 4] = acc;
    if (kc == 0) {
        float c = 0.f;
#pragma unroll
        for (int d = 0; d < 8; d++)
            c += g_cnt2[base + (((d >> 2) & 1) << 12) + (((d >> 1) & 1) << 6) + (d & 1)];
        g_cnt4[s4] = c;
    }
}

__global__ __launch_bounds__(256) void reduce8_kernel() {
    int t = blockIdx.x * 256 + threadIdx.x;   // NSEG8 * 16 tasks
    int kc = t & 15;
    int s8 = t >> 4;
    int b = s8 >> 12, x = (s8 >> 8) & 15, y = (s8 >> 4) & 15, z = s8 & 15;
    int base = (b << 15) | ((x << 1) << 10) | ((y << 1) << 5) | (z << 1);
    float4 acc = make_float4(0.f, 0.f, 0.f, 0.f);
#pragma unroll
    for (int d = 0; d < 8; d++) {
        int s4 = base + (((d >> 2) & 1) << 10) + (((d >> 1) & 1) << 5) + (d & 1);
        float4 v = *(const float4*)&g_sums4[(long)s4 * 64 + kc * 4];
        acc.x += v.x; acc.y += v.y; acc.z += v.z; acc.w += v.w;
    }
    *(float4*)&g_sums8[(long)s8 * 64 + kc * 4] = acc;
    if (kc == 0) {
        float c = 0.f;
#pragma unroll
        for (int d = 0; d < 8; d++)
            c += g_cnt4[base + (((d >> 2) & 1) << 10) + (((d >> 1) & 1) << 5) + (d & 1)];
        g_cnt8[s8] = c;
    }
}

// ---------------- kernel 3a: l0 partial reduce (64 blocks) ----------------
__global__ __launch_bounds__(256) void l0_part_kernel() {
    int blk = blockIdx.x;           // 0..63
    int b = blk >> 4, part = blk & 15;
    int tid = threadIdx.x;
    __shared__ float sm[4][64];
    __shared__ float scnt[256];

    int c = tid & 63, g = tid >> 6;
    int row0 = b * 4096 + part * 256;
    const float* base = g_sums8 + (long)row0 * 64;
    float acc = 0.f;
    for (int s = g; s < 256; s += 4) acc += base[s * 64 + c];
    sm[g][c] = acc;

    float ca = 0.f;
    for (int s = tid; s < 256; s += 256) ca += g_cnt8[row0 + s];
    scnt[tid] = ca;
    __syncthreads();

    for (int off = 128; off > 0; off >>= 1) {
        if (tid < off) scnt[tid] += scnt[tid + off];
        __syncthreads();
    }
    if (tid < 64)
        g_l0part[blk * 64 + tid] = sm[0][tid] + sm[1][tid] + sm[2][tid] + sm[3][tid];
    if (tid == 0)
        g_l0cnt[blk] = scnt[0];
}

// ---------------- kernel 3b: l0 final projection (4 blocks) ----------------
__global__ __launch_bounds__(128) void l0_final_kernel(
    const float* __restrict__ W, const float* __restrict__ bias)
{
    int b = blockIdx.x;
    int tid = threadIdx.x;
    __shared__ float smean[64];
    __shared__ float scnt_sh;

    if (tid < 64) {
        float s = 0.f;
#pragma unroll
        for (int k = 0; k < 16; k++) s += g_l0part[(b * 16 + k) * 64 + tid];
        smean[tid] = s;
    }
    if (tid == 0) {
        float c = 0.f;
#pragma unroll
        for (int k = 0; k < 16; k++) c += g_l0cnt[b * 16 + k];
        scnt_sh = fmaxf(c, 1.0f);
    }
    __syncthreads();
    if (tid < 64) smean[tid] /= scnt_sh;
    __syncthreads();
    if (tid < 96) {
        float a = bias[tid];
        const float* wr = W + tid * 256;  // global block = cols [0,64)
#pragma unroll 8
        for (int k = 0; k < 64; k++) a += wr[k] * smean[k];
        g_base0[b * COUT + tid] = a;
    }
}

// ---------------- shared HMMA tile machinery ----------------
#define A_STRIDE 72   // halves per A row, padded
#define B_U32    36   // uint32 per B row (padded: bank = 4*grp+qid, conflict-free)
#define TILE_PTS 128  // points/segments per block
#define TTHREADS 256  // threads per block (8 warps)
#define D_STRIDE 100  // floats per D row in smem (400B, 16B-aligned)

#define SMEM_AH_OFF 0
#define SMEM_AL_OFF (TILE_PTS * A_STRIDE * 2)
#define SMEM_BH_OFF (2 * TILE_PTS * A_STRIDE * 2)
#define SMEM_BL_OFF (SMEM_BH_OFF + 96 * B_U32 * 4)
#define SMEM_DYN    (SMEM_BL_OFF + 96 * B_U32 * 4)
// D tile (reuses A/B region after MMA): TILE_PTS * D_STRIDE * 4 = 51200 <= SMEM_DYN

// stage pre-split W level block into smem (conflict-free layout)
__device__ __forceinline__ void stage_W(uint32_t* shBh, uint32_t* shBl,
                                        const uint32_t* __restrict__ Wh,
                                        const uint32_t* __restrict__ Wl,
                                        int tid)
{
    for (int idx = tid; idx < 3072; idx += TTHREADS) {
        int o = idx >> 5, j = idx & 31;
        shBh[o * B_U32 + j] = Wh[idx];
        shBl[o * B_U32 + j] = Wl[idx];
    }
}

// core bf16x3 MMA over staged A (TILE_PTS rows) and W (96 rows), per-warp m16 x n96
__device__ __forceinline__ void mma_tile(
    const __nv_bfloat16* shAh, const __nv_bfloat16* shAl,
    const uint32_t* shBh, const uint32_t* shBl,
    int warp_m, int grp, int qid, float acc[12][4])
{
#pragma unroll
    for (int ks = 0; ks < 4; ks++) {
        int k0 = ks * 16 + qid * 2;
        int ra = (warp_m + grp) * A_STRIDE;
        int rb = (warp_m + grp + 8) * A_STRIDE;
        uint32_t ah0 = *(const uint32_t*)&shAh[ra + k0];
        uint32_t ah1 = *(const uint32_t*)&shAh[rb + k0];
        uint32_t ah2 = *(const uint32_t*)&shAh[ra + k0 + 8];
        uint32_t ah3 = *(const uint32_t*)&shAh[rb + k0 + 8];
        uint32_t al0 = *(const uint32_t*)&shAl[ra + k0];
        uint32_t al1 = *(const uint32_t*)&shAl[rb + k0];
        uint32_t al2 = *(const uint32_t*)&shAl[ra + k0 + 8];
        uint32_t al3 = *(const uint32_t*)&shAl[rb + k0 + 8];
        int wb = ks * 8 + qid;
#pragma unroll
        for (int t = 0; t < 12; t++) {
            int n = t * 8 + grp;
            uint32_t bh0 = shBh[n * B_U32 + wb];
            uint32_t bh1 = shBh[n * B_U32 + wb + 4];
            uint32_t bl0 = shBl[n * B_U32 + wb];
            uint32_t bl1 = shBl[n * B_U32 + wb + 4];
            hmma16816(acc[t][0], acc[t][1], acc[t][2], acc[t][3],
                      ah0, ah1, ah2, ah3, bh0, bh1);
            hmma16816(acc[t][0], acc[t][1], acc[t][2], acc[t][3],
                      ah0, ah1, ah2, ah3, bl0, bl1);
            hmma16816(acc[t][0], acc[t][1], acc[t][2], acc[t][3],
                      al0, al1, al2, al3, bh0, bh1);
        }
    }
}

// ---------------- HMMA transform for levels 8 and 4 (bf16x3) ----------------
template <int LEVEL>
__global__ __launch_bounds__(TTHREADS) void transform_hmma_kernel()
{
    extern __shared__ __align__(16) char dynsmem[];
    __nv_bfloat16* sh_Ah = (__nv_bfloat16*)(dynsmem + SMEM_AH_OFF);
    __nv_bfloat16* sh_Al = (__nv_bfloat16*)(dynsmem + SMEM_AL_OFF);
    uint32_t* sh_Bh = (uint32_t*)(dynsmem + SMEM_BH_OFF);
    uint32_t* sh_Bl = (uint32_t*)(dynsmem + SMEM_BL_OFF);

    int tid  = threadIdx.x;
    int wid  = tid >> 5;
    int lane = tid & 31;
    int base = blockIdx.x * TILE_PTS;

    const float* SUMS = (LEVEL == 4) ? g_sums4 : g_sums8;
    const float* CNT  = (LEVEL == 4) ? g_cnt4  : g_cnt8;
    const int LIDX = (LEVEL == 4) ? 1 : 2;

    stage_W(sh_Bh, sh_Bl, g_Wh32 + LIDX * 3072, g_Wl32 + LIDX * 3072, tid);

    for (int it = tid; it < TILE_PTS * 16; it += TTHREADS) {
        int slot = it >> 4, kc = it & 15;
        int s = base + slot;
        float inv = 1.0f / fmaxf(CNT[s], 1.0f);
        float4 v = *(const float4*)&SUMS[(long)s * 64 + kc * 4];
        uint32_t h0, l0, h1, l1;
        split2(v.x * inv, v.y * inv, h0, l0);
        split2(v.z * inv, v.w * inv, h1, l1);
        uint32_t* dh = (uint32_t*)&sh_Ah[slot * A_STRIDE + kc * 4];
        uint32_t* dl = (uint32_t*)&sh_Al[slot * A_STRIDE + kc * 4];
        dh[0] = h0; dh[1] = h1;
        dl[0] = l0; dl[1] = l1;
    }
    __syncthreads();

    int warp_m = wid * 16;
    int grp = lane >> 2;
    int qid = lane & 3;

    float acc[12][4];
#pragma unroll
    for (int t = 0; t < 12; t++)
#pragma unroll
        for (int j = 0; j < 4; j++) acc[t][j] = 0.f;

    mma_tile(sh_Ah, sh_Al, sh_Bh, sh_Bl, warp_m, grp, qid, acc);

    // epilogue
    int slot0 = warp_m + grp;
    int slot1 = slot0 + 8;
    int s0 = base + slot0;
    int s1 = base + slot1;

    const float* p0;
    const float* p1;
    float* zout;
    if (LEVEL == 8) {
        p0 = &g_base0[(s0 >> 12) * COUT];
        p1 = &g_base0[(s1 >> 12) * COUT];
        zout = g_Z8;
    } else {
        int bb0 = s0 >> 15, xx0 = (s0 >> 10) & 31, yy0 = (s0 >> 5) & 31, zz0 = s0 & 31;
        int bb1 = s1 >> 15, xx1 = (s1 >> 10) & 31, yy1 = (s1 >> 5) & 31, zz1 = s1 & 31;
        p0 = &g_Z8[(long)((bb0 << 12) | ((xx0 >> 1) << 8) | ((yy0 >> 1) << 4) | (zz0 >> 1)) * COUT];
        p1 = &g_Z8[(long)((bb1 << 12) | ((xx1 >> 1) << 8) | ((yy1 >> 1) << 4) | (zz1 >> 1)) * COUT];
        zout = g_Z4;
    }
    float* d0 = zout + (long)s0 * COUT;
    float* d1 = zout + (long)s1 * COUT;

#pragma unroll
    for (int t = 0; t < 12; t++) {
        int c = t * 8 + qid * 2;
        float2 za = *(const float2*)&p0[c];
        float2 zb = *(const float2*)&p1[c];
        *(float2*)&d0[c] = make_float2(acc[t][0] + za.x, acc[t][1] + za.y);
        *(float2*)&d1[c] = make_float2(acc[t][2] + zb.x, acc[t][3] + zb.y);
    }
}

// ---------------- fused level-2 transform + output (bf16x3 HMMA) ----------------
// D = W2 @ sums2 rows (raw), scaled by 1/cnt in the epilogue.
__global__ __launch_bounds__(TTHREADS) void fused_mma_kernel(float* __restrict__ out)
{
    extern __shared__ __align__(16) char dynsmem[];
    __nv_bfloat16* sh_Ah = (__nv_bfloat16*)(dynsmem + SMEM_AH_OFF);
    __nv_bfloat16* sh_Al = (__nv_bfloat16*)(dynsmem + SMEM_AL_OFF);
    uint32_t* sh_Bh = (uint32_t*)(dynsmem + SMEM_BH_OFF);
    uint32_t* sh_Bl = (uint32_t*)(dynsmem + SMEM_BL_OFF);

    __shared__ int   s_s4[TILE_PTS];
    __shared__ float s_inv[TILE_PTS];

    int tid  = threadIdx.x;
    int wid  = tid >> 5;
    int lane = tid & 31;
    int pbase = blockIdx.x * TILE_PTS;

    // ---- phase 1: issue all sums2 gathers FIRST (max MLP, no sync dependency) ----
    float4 va[8];
#pragma unroll
    for (int i = 0; i < 8; i++) {
        int it = tid + i * TTHREADS;
        int slot = it >> 4, kc = it & 15;
        int s2 = __ldg(&g_seg2[pbase + slot]);        // 16-lane broadcast
        va[i] = __ldg((const float4*)&g_sums2[(long)s2 * 64 + kc * 4]);
    }

    // ---- phase 2: overlap W staging + per-point index/scale fill ----
    if (tid < TILE_PTS) {
        int s2 = g_seg2[pbase + tid];
        int bb = s2 >> 18, xx = (s2 >> 12) & 63, yy = (s2 >> 6) & 63, zz = s2 & 63;
        s_s4[tid] = (bb << 15) | ((xx >> 1) << 10) | ((yy >> 1) << 5) | (zz >> 1);
        s_inv[tid] = 1.0f / fmaxf(g_cnt2[s2], 1.0f);
    }
    stage_W(sh_Bh, sh_Bl, g_Wh32, g_Wl32, tid);   // level-2 block (LIDX 0)

    // ---- phase 3: convert gathered raw sums -> bf16 hi/lo in smem ----
#pragma unroll
    for (int i = 0; i < 8; i++) {
        int it = tid + i * TTHREADS;
        int slot = it >> 4, kc = it & 15;
        uint32_t h0, l0, h1, l1;
        split2(va[i].x, va[i].y, h0, l0);
        split2(va[i].z, va[i].w, h1, l1);
        uint32_t* dh = (uint32_t*)&sh_Ah[slot * A_STRIDE + kc * 4];
        uint32_t* dl = (uint32_t*)&sh_Al[slot * A_STRIDE + kc * 4];
        dh[0] = h0; dh[1] = h1;
        dl[0] = l0; dl[1] = l1;
    }
    __syncthreads();

    int warp_m = wid * 16;
    int grp = lane >> 2;
    int qid = lane & 3;

    float acc[12][4];
#pragma unroll
    for (int t = 0; t < 12; t++)
#pragma unroll
        for (int j = 0; j < 4; j++) acc[t][j] = 0.f;

    mma_tile(sh_Ah, sh_Al, sh_Bh, sh_Bl, warp_m, grp, qid, acc);

    // ---- coalesced epilogue: stage D in smem (reusing A/B region), then
    //      stream (D * inv + Z4) with coalesced float4 accesses ----
    __syncthreads();   // all smem A/B reads done; safe to overwrite
    float* sh_D = (float*)dynsmem;
    {
        int r0 = warp_m + grp, r1 = r0 + 8;
#pragma unroll
        for (int t = 0; t < 12; t++) {
            int c = t * 8 + qid * 2;
            *(float2*)&sh_D[r0 * D_STRIDE + c] = make_float2(acc[t][0], acc[t][1]);
            *(float2*)&sh_D[r1 * D_STRIDE + c] = make_float2(acc[t][2], acc[t][3]);
        }
    }
    __syncthreads();

    for (int it = tid; it < TILE_PTS * 24; it += TTHREADS) {
        int slot = it / 24;
        int ch = it - slot * 24;
        float inv = s_inv[slot];
        float4 d = *(const float4*)&sh_D[slot * D_STRIDE + ch * 4];
        float4 z = *(const float4*)&g_Z4[(long)s_s4[slot] * COUT + ch * 4];
        float4 o = make_float4(fmaf(d.x, inv, z.x), fmaf(d.y, inv, z.y),
                               fmaf(d.z, inv, z.z), fmaf(d.w, inv, z.w));
        *(float4*)&out[(long)(pbase + slot) * COUT + ch * 4] = o;
    }
}

// ---------------- launcher ----------------
extern "C" void kernel_launch(void* const* d_in, const int* in_sizes, int n_in,
                              void* d_out, int out_size)
{
    const float* feats  = (const float*)d_in[0];
    const int*   coords = (const int*)d_in[1];
    const int*   batch  = (const int*)d_in[2];
    const float* W      = (const float*)d_in[3];
    const float* bias   = (const float*)d_in[4];

    // opt into >48KB dynamic smem (attribute set, not an allocation; idempotent)
    static bool attr_done = false;
    if (!attr_done) {
        cudaFuncSetAttribute(fused_mma_kernel,
                             cudaFuncAttributeMaxDynamicSharedMemorySize, SMEM_DYN);
        cudaFuncSetAttribute(transform_hmma_kernel<4>,
                             cudaFuncAttributeMaxDynamicSharedMemorySize, SMEM_DYN);
        cudaFuncSetAttribute(transform_hmma_kernel<8>,
                             cudaFuncAttributeMaxDynamicSharedMemorySize, SMEM_DYN);
        attr_done = true;
    }

    zero_sums_kernel<<<2048, 256>>>();
    zero_cnt_kernel<<<256, 256>>>();
    split_w_kernel<<<36, 256>>>(W);
    scatter_kernel<<<8192, 256>>>((const float4*)feats, coords, batch);
    reduce4_kernel<<<(NSEG4 * 16) / 256, 256>>>();
    reduce8_kernel<<<(NSEG8 * 16) / 256, 256>>>();
    l0_part_kernel<<<64, 256>>>();
    l0_final_kernel<<<NB, 128>>>(W, bias);
    transform_hmma_kernel<8><<<NSEG8 / TILE_PTS, TTHREADS, SMEM_DYN>>>();
    transform_hmma_kernel<4><<<NSEG4 / TILE_PTS, TTHREADS, SMEM_DYN>>>();
    fused_mma_kernel<<<NPTS / TILE_PTS, TTHREADS, SMEM_DYN>>>((float*)d_out);
}